// round 2
// baseline (speedup 1.0000x reference)
#include <cuda_runtime.h>
#include <cuda_fp16.h>
#include <cstdint>

// ---------------- problem constants ----------------
#define K_ORIG  20000
#define K_PAD   20032
#define M_TOTAL 2048
#define N_TOTAL 512
#define MT 128
#define NT 64
#define KT 64
#define NCHUNK (K_PAD / KT)      // 313

#define A_BYTES (MT * KT * 2)    // 16384
#define B_BYTES (NT * KT * 2)    // 8192
#define STAGE   (A_BYTES + B_BYTES)
#define SMEM_BYTES (1024 + 2 * STAGE)

// ---------------- device scratch (fp16 operands) ----------------
__device__ __half g_xh[(size_t)M_TOTAL * K_PAD];   // x   [M, K_PAD] row-major
__device__ __half g_eh[(size_t)N_TOTAL * K_PAD];   // E^T [N, K_PAD] K-major

// ---------------- helpers ----------------
__device__ __forceinline__ uint32_t smem_u32(const void* p) {
    uint32_t a;
    asm("{ .reg .u64 t; cvta.to.shared.u64 t, %1; cvt.u32.u64 %0, t; }"
        : "=r"(a) : "l"(p));
    return a;
}

__device__ __forceinline__ uint32_t swz(uint32_t off) {
    return off ^ ((off >> 3) & 0x70u);     // 128B-period XOR swizzle
}

__device__ __forceinline__ void cp16(uint32_t sa, const void* gp) {
    asm volatile("cp.async.cg.shared.global [%0], [%1], 16;" :: "r"(sa), "l"(gp));
}

__device__ __forceinline__ void ldsm4(uint32_t* r, uint32_t sa) {
    asm volatile("ldmatrix.sync.aligned.m8n8.x4.shared.b16 {%0,%1,%2,%3}, [%4];"
                 : "=r"(r[0]), "=r"(r[1]), "=r"(r[2]), "=r"(r[3]) : "r"(sa));
}

__device__ __forceinline__ void mma16816(float* d, const uint32_t* a,
                                         const uint32_t* b) {
    asm volatile(
        "mma.sync.aligned.m16n8k16.row.col.f32.f16.f16.f32 "
        "{%0,%1,%2,%3}, {%4,%5,%6,%7}, {%8,%9}, {%0,%1,%2,%3};"
        : "+f"(d[0]), "+f"(d[1]), "+f"(d[2]), "+f"(d[3])
        : "r"(a[0]), "r"(a[1]), "r"(a[2]), "r"(a[3]), "r"(b[0]), "r"(b[1]));
}

// ---------------- conversion kernels ----------------
// x fp32 [M, 20000] -> fp16 [M, 20032] (zero-padded tail)
__global__ void convert_x_kernel(const float* __restrict__ x) {
    unsigned idx4 = blockIdx.x * 256u + threadIdx.x;
    const unsigned per_row = K_PAD / 4;             // 5008
    if (idx4 >= (unsigned)M_TOTAL * per_row) return;
    unsigned m = idx4 / per_row;
    unsigned k = (idx4 - m * per_row) * 4u;
    float4 v;
    if (k + 3 < K_ORIG) {
        v = *reinterpret_cast<const float4*>(x + (size_t)m * K_ORIG + k);
    } else {
        v.x = v.y = v.z = v.w = 0.0f;
    }
    __half2 h0 = __floats2half2_rn(v.x, v.y);
    __half2 h1 = __floats2half2_rn(v.z, v.w);
    uint2 pk;
    pk.x = *reinterpret_cast<uint32_t*>(&h0);
    pk.y = *reinterpret_cast<uint32_t*>(&h1);
    *reinterpret_cast<uint2*>(g_xh + (size_t)m * K_PAD + k) = pk;
}

// E fp32 [20000, 512] -> E^T fp16 [512, 20032] (K-major, zero-padded tail)
__global__ void convert_e_kernel(const float* __restrict__ e) {
    __shared__ float tile[32][33];
    const int kb = blockIdx.x * 32;
    const int hb = blockIdx.y * 32;
    const int tx = threadIdx.x, ty = threadIdx.y;
    #pragma unroll
    for (int i = ty; i < 32; i += 8) {
        int k = kb + i;
        tile[i][tx] = (k < K_ORIG) ? e[(size_t)k * N_TOTAL + hb + tx] : 0.0f;
    }
    __syncthreads();
    #pragma unroll
    for (int i = ty; i < 32; i += 8) {
        int h = hb + i;
        int k = kb + tx;
        g_eh[(size_t)h * K_PAD + k] = __float2half_rn(tile[tx][i]);
    }
}

// ---------------- fp16 mma.sync GEMM ----------------
// out[m, n] = (sum_k x[m,k] * E[k,n]) / K_ORIG + bias[n]
__global__ void __launch_bounds__(256, 1)
gemm_fp16_kernel(const float* __restrict__ bias, float* __restrict__ out) {
    extern __shared__ char smem_raw[];
    uint32_t sb = smem_u32(smem_raw);
    sb = (sb + 1023u) & ~1023u;

    const int tid = threadIdx.x;
    const int wid = tid >> 5;
    const int lid = tid & 31;
    const int m0 = blockIdx.x * MT;
    const int n0 = blockIdx.y * NT;

    const __half* __restrict__ xg = g_xh + (size_t)m0 * K_PAD;
    const __half* __restrict__ eg = g_eh + (size_t)n0 * K_PAD;

    // ---- producer indexing: 256 threads, 16B each ----
    const int c16 = tid & 7;        // 16B column within 128B row
    const int r32 = tid >> 3;       // 0..31

    auto load_chunk = [&](int c) {
        const uint32_t st = sb + (uint32_t)(c & 1) * (uint32_t)STAGE;
        const int k0 = c * KT;
        #pragma unroll
        for (int i = 0; i < 4; i++) {          // A: 128 rows
            const int row = r32 + i * 32;
            const uint32_t sa = st + swz((uint32_t)(row * 128 + c16 * 16));
            cp16(sa, xg + (size_t)row * K_PAD + (k0 + c16 * 8));
        }
        #pragma unroll
        for (int i = 0; i < 2; i++) {          // B: 64 rows
            const int row = r32 + i * 32;
            const uint32_t sa = st + (uint32_t)A_BYTES
                              + swz((uint32_t)(row * 128 + c16 * 16));
            cp16(sa, eg + (size_t)row * K_PAD + (k0 + c16 * 8));
        }
        asm volatile("cp.async.commit_group;" ::: "memory");
    };

    // ---- consumer indexing ----
    const int wm = wid & 3;         // 4 warps along M
    const int wn = wid >> 2;        // 2 warps along N
    const int mbase = wm * 32;
    const int nbase = wn * 32;

    // ldmatrix lane address components (see fragment-mapping derivation)
    const int a_row   = mbase + (lid & 15);
    const uint32_t a_kh = (uint32_t)(lid >> 4) * 16u;        // k-half byte off
    const int b_row   = nbase + ((lid >> 4) * 8) + (lid & 7);
    const uint32_t b_kh = (uint32_t)((lid >> 3) & 1) * 16u;

    float acc[2][4][4];
    #pragma unroll
    for (int i = 0; i < 2; i++)
        #pragma unroll
        for (int j = 0; j < 4; j++)
            #pragma unroll
            for (int q = 0; q < 4; q++) acc[i][j][q] = 0.0f;

    load_chunk(0);

    for (int c = 0; c < NCHUNK; c++) {
        if (c + 1 < NCHUNK) {
            load_chunk(c + 1);
            asm volatile("cp.async.wait_group 1;" ::: "memory");
        } else {
            asm volatile("cp.async.wait_group 0;" ::: "memory");
        }
        __syncthreads();

        const uint32_t st = sb + (uint32_t)(c & 1) * (uint32_t)STAGE;
        #pragma unroll
        for (int ks = 0; ks < 4; ks++) {
            const uint32_t kb = (uint32_t)ks * 32u;   // byte offset of k16 step

            uint32_t af[2][4];
            #pragma unroll
            for (int im = 0; im < 2; im++) {
                const uint32_t off = (uint32_t)((a_row + im * 16) * 128) + kb + a_kh;
                ldsm4(af[im], st + swz(off));
            }
            uint32_t bf[2][4];
            #pragma unroll
            for (int ib = 0; ib < 2; ib++) {
                const uint32_t off = (uint32_t)((b_row + ib * 16) * 128) + kb + b_kh;
                ldsm4(bf[ib], st + (uint32_t)A_BYTES + swz(off));
            }
            #pragma unroll
            for (int im = 0; im < 2; im++) {
                #pragma unroll
                for (int in = 0; in < 4; in++) {
                    mma16816(acc[im][in], af[im], &bf[in >> 1][(in & 1) * 2]);
                }
            }
        }
        __syncthreads();
    }

    // ---- epilogue ----
    const float inv = 1.0f / (float)K_ORIG;
    const int mrow = m0 + mbase + (lid >> 2);
    const int ncol = n0 + nbase + (lid & 3) * 2;
    #pragma unroll
    for (int im = 0; im < 2; im++) {
        #pragma unroll
        for (int in = 0; in < 4; in++) {
            const int m = mrow + im * 16;
            const int n = ncol + in * 8;
            const float b0 = __ldg(&bias[n]);
            const float b1 = __ldg(&bias[n + 1]);
            float2 v0, v1;
            v0.x = acc[im][in][0] * inv + b0;
            v0.y = acc[im][in][1] * inv + b1;
            v1.x = acc[im][in][2] * inv + b0;
            v1.y = acc[im][in][3] * inv + b1;
            *reinterpret_cast<float2*>(&out[(size_t)m * N_TOTAL + n]) = v0;
            *reinterpret_cast<float2*>(&out[(size_t)(m + 8) * N_TOTAL + n]) = v1;
        }
    }
}

// ---------------- launch ----------------
extern "C" void kernel_launch(void* const* d_in, const int* in_sizes, int n_in,
                              void* d_out, int out_size) {
    (void)in_sizes; (void)n_in; (void)out_size;
    const float* x    = (const float*)d_in[0];
    const float* e    = (const float*)d_in[1];
    const float* bias = (const float*)d_in[2];
    float* out = (float*)d_out;

    cudaFuncSetAttribute(gemm_fp16_kernel,
                         cudaFuncAttributeMaxDynamicSharedMemorySize, SMEM_BYTES);

    {
        int tot4 = M_TOTAL * (K_PAD / 4);
        convert_x_kernel<<<(tot4 + 255) / 256, 256>>>(x);
    }
    convert_e_kernel<<<dim3(K_PAD / 32, N_TOTAL / 32), dim3(32, 8)>>>(e);
    gemm_fp16_kernel<<<dim3(M_TOTAL / MT, N_TOTAL / NT), 256, SMEM_BYTES>>>(bias, out);
}